// round 1
// baseline (speedup 1.0000x reference)
#include <cuda_runtime.h>
#include <cstdint>

// Problem constants (fixed by setup_inputs)
#define BATCH   4096
#define N_IN    512
#define N_TOT   2048
#define N_EVAL  1536
#define N_OUT   256
#define GROW    1536              // N_TOT - N_IN (growing columns, smem-resident)

#define WARPS_PER_BLOCK 8
#define ROWS_PER_WARP   2
#define ROWS_PER_BLOCK  (WARPS_PER_BLOCK * ROWS_PER_WARP)   // 16
#define THREADS         (WARPS_PER_BLOCK * 32)              // 256
#define GRID            (BATCH / ROWS_PER_BLOCK)            // 256
#define SMEM_BYTES      (ROWS_PER_BLOCK * GROW * 4)         // 98304

__device__ __forceinline__ float dot4(float4 a, float4 b) {
    return a.x * b.x + a.y * b.y + a.z * b.z + a.w * b.w;
}

__global__ __launch_bounds__(THREADS, 2)
void neat_scan_kernel(const float* __restrict__ x,
                      const float* __restrict__ W,
                      const float* __restrict__ b,
                      float* __restrict__ out)
{
    extern __shared__ float smem[];   // [ROWS_PER_BLOCK][GROW]
    const int lane = threadIdx.x & 31;
    const int warp = threadIdx.x >> 5;
    const int r0 = blockIdx.x * ROWS_PER_BLOCK + 2 * warp;   // this warp's batch rows

    float* s0 = smem + (size_t)(2 * warp) * GROW;
    float* s1 = s0 + GROW;

    // --- zero-init growing region (W mask makes over-read tiles exact) ---
    {
        float4 z4 = make_float4(0.f, 0.f, 0.f, 0.f);
        float4* v0 = (float4*)s0;
        float4* v1 = (float4*)s1;
#pragma unroll
        for (int k = 0; k < GROW / 128; k++) {        // 12 float4 per lane per row
            v0[k * 32 + lane] = z4;
            v1[k * 32 + lane] = z4;
        }
    }

    // --- input activations (columns 0..511) live in registers ---
    float4 xr0[4], xr1[4];
    {
        const float4* x0 = (const float4*)(x + (size_t)r0 * N_IN);
        const float4* x1 = (const float4*)(x + (size_t)(r0 + 1) * N_IN);
#pragma unroll
        for (int k = 0; k < 4; k++) {
            xr0[k] = x0[k * 32 + lane];
            xr1[k] = x1[k * 32 + lane];
        }
    }
    __syncwarp();

    const float4* sv0 = (const float4*)s0;
    const float4* sv1 = (const float4*)s1;

    // --- sequential node scan; warp-private, no cross-warp sync ---
    for (int i = 0; i < N_EVAL; i++) {
        const float4* w4 = (const float4*)(W + (size_t)i * N_TOT);
        float a0 = 0.f, a1 = 0.f;

        // fixed input-part contribution (registers)
#pragma unroll
        for (int k = 0; k < 4; k++) {
            float4 w = w4[k * 32 + lane];
            a0 += dot4(w, xr0[k]);
            a1 += dot4(w, xr1[k]);
        }

        // growing-part contribution (smem); tiles beyond i are zero (mask+init)
        const int kg = (i + 127) >> 7;
#pragma unroll 2
        for (int k = 0; k < kg; k++) {
            float4 w  = w4[128 + k * 32 + lane];
            float4 v0 = sv0[k * 32 + lane];
            float4 v1 = sv1[k * 32 + lane];
            a0 += dot4(w, v0);
            a1 += dot4(w, v1);
        }

        // warp reduction (butterfly -> all lanes hold totals)
#pragma unroll
        for (int off = 16; off; off >>= 1) {
            a0 += __shfl_xor_sync(0xffffffffu, a0, off);
            a1 += __shfl_xor_sync(0xffffffffu, a1, off);
        }

        const float bi = __ldg(b + i);
        float t0 = fminf(fmaxf(5.f * (a0 + bi), -60.f), 60.f);
        float t1 = fminf(fmaxf(5.f * (a1 + bi), -60.f), 60.f);
        float o0 = 1.f / (1.f + __expf(-t0));
        float o1 = 1.f / (1.f + __expf(-t1));

        if (lane == 0) { s0[i] = o0; s1[i] = o1; }
        __syncwarp();
    }

    // --- emit last N_OUT columns (grow cols GROW-N_OUT .. GROW-1) ---
    {
        float4*       d0 = (float4*)(out + (size_t)r0 * N_OUT);
        float4*       d1 = (float4*)(out + (size_t)(r0 + 1) * N_OUT);
        const float4* q0 = (const float4*)(s0 + (GROW - N_OUT));
        const float4* q1 = (const float4*)(s1 + (GROW - N_OUT));
#pragma unroll
        for (int k = 0; k < N_OUT / 128; k++) {       // 2 float4 per lane per row
            d0[k * 32 + lane] = q0[k * 32 + lane];
            d1[k * 32 + lane] = q1[k * 32 + lane];
        }
    }
}

extern "C" void kernel_launch(void* const* d_in, const int* in_sizes, int n_in,
                              void* d_out, int out_size)
{
    const float* x = (const float*)d_in[0];
    const float* W = (const float*)d_in[1];
    const float* b = (const float*)d_in[2];
    float* out = (float*)d_out;

    cudaFuncSetAttribute(neat_scan_kernel,
                         cudaFuncAttributeMaxDynamicSharedMemorySize, SMEM_BYTES);
    neat_scan_kernel<<<GRID, THREADS, SMEM_BYTES>>>(x, W, b, out);
}

// round 4
// speedup vs baseline: 1.9052x; 1.9052x over previous
#include <cuda_runtime.h>
#include <cstdint>

// Problem constants (fixed by setup_inputs)
#define BATCH   4096
#define N_IN    512
#define N_TOT   2048
#define N_EVAL  1536
#define N_OUT   256
#define GROW    1536

#define G               8                     // nodes per group
#define NGROUPS         (N_EVAL / G)          // 192
#define WARPS_PER_BLOCK 8
#define ROWS_PER_WARP   2
#define ROWS_PER_BLOCK  (WARPS_PER_BLOCK * ROWS_PER_WARP)   // 16
#define THREADS         (WARPS_PER_BLOCK * 32)              // 256
#define GRID            (BATCH / ROWS_PER_BLOCK)            // 256
#define SMEM_BYTES      (ROWS_PER_BLOCK * GROW * 4)         // 98304

typedef unsigned long long u64;

// Packed f32x2 FMA (sm_100+): acc.lo += a.lo*b.lo; acc.hi += a.hi*b.hi
__device__ __forceinline__ void ffma2(u64 &acc, u64 a, u64 b) {
    asm("fma.rn.f32x2 %0, %1, %2, %0;" : "+l"(acc) : "l"(a), "l"(b));
}
__device__ __forceinline__ float2 unpack2(u64 v) {
    float lo, hi;
    asm("mov.b64 {%0, %1}, %2;" : "=f"(lo), "=f"(hi) : "l"(v));
    return make_float2(lo, hi);
}
__device__ __forceinline__ float sigmoid5(float z) {
    float t = fminf(fmaxf(5.0f * z, -60.0f), 60.0f);
    return 1.0f / (1.0f + __expf(-t));
}

__global__ __launch_bounds__(THREADS, 2)
void neat_group_kernel(const float* __restrict__ x,
                       const float* __restrict__ W,
                       const float* __restrict__ b,
                       float* __restrict__ out)
{
    extern __shared__ float smem[];            // [16 rows][GROW]
    const int lane = threadIdx.x & 31;
    const int warp = threadIdx.x >> 5;
    const int r0 = blockIdx.x * ROWS_PER_BLOCK + 2 * warp;

    float* s0 = smem + (size_t)(2 * warp) * GROW;
    float* s1 = s0 + GROW;

    // --- zero-init growing region (zero acts make over-read tiles exact) ---
    {
        float4 z4 = make_float4(0.f, 0.f, 0.f, 0.f);
#pragma unroll
        for (int k = 0; k < GROW / 128; k++) {
            ((float4*)s0)[k * 32 + lane] = z4;
            ((float4*)s1)[k * 32 + lane] = z4;
        }
    }

    // --- input activations (cols 0..511) in registers, packed f32x2 pairs ---
    ulonglong2 xr0[4], xr1[4];
    {
        const ulonglong2* xp0 = (const ulonglong2*)(x + (size_t)r0 * N_IN);
        const ulonglong2* xp1 = (const ulonglong2*)(x + (size_t)(r0 + 1) * N_IN);
#pragma unroll
        for (int t = 0; t < 4; t++) {
            xr0[t] = xp0[t * 32 + lane];
            xr1[t] = xp1[t * 32 + lane];
        }
    }
    __syncwarp();

    const ulonglong2* sv0 = (const ulonglong2*)s0;
    const ulonglong2* sv1 = (const ulonglong2*)s1;

    // ================= node-group scan =================
    for (int g = 0; g < NGROUPS; g++) {
        const int e0 = G * g;                  // first EVAL index of group (W row)
        const int i0 = N_IN + e0;              // first GLOBAL node id (W column)

        u64 acc0[G], acc1[G];
#pragma unroll
        for (int n = 0; n < G; n++) { acc0[n] = 0ull; acc1[n] = 0ull; }

        // --- bulk: input part from registers (4 tiles of 128 cols) ---
#pragma unroll
        for (int t = 0; t < 4; t++) {
            const ulonglong2 a0 = xr0[t];
            const ulonglong2 a1 = xr1[t];
#pragma unroll
            for (int n = 0; n < G; n++) {
                const ulonglong2 w =
                    ((const ulonglong2*)(W + (size_t)(e0 + n) * N_TOT))[t * 32 + lane];
                ffma2(acc0[n], w.x, a0.x); ffma2(acc0[n], w.y, a0.y);
                ffma2(acc1[n], w.x, a1.x); ffma2(acc1[n], w.y, a1.y);
            }
        }

        // --- bulk: growing part from smem; tiles rounded up past the group.
        //     Unwritten act columns are zero, so masked-W overlap is exact. ---
        const int ntg = (g >> 4) + 1;          // ceil((8g+8)/128) tiles
        for (int k = 0; k < ntg; k++) {
            const ulonglong2 a0 = sv0[k * 32 + lane];
            const ulonglong2 a1 = sv1[k * 32 + lane];
#pragma unroll
            for (int n = 0; n < G; n++) {
                const ulonglong2 w =
                    ((const ulonglong2*)(W + (size_t)(e0 + n) * N_TOT))[128 + k * 32 + lane];
                ffma2(acc0[n], w.x, a0.x); ffma2(acc0[n], w.y, a0.y);
                ffma2(acc1[n], w.x, a1.x); ffma2(acc1[n], w.y, a1.y);
            }
        }

        // --- butterfly reduce 16 partials (once per 8 nodes) ---
        float z0[G], z1[G];
#pragma unroll
        for (int n = 0; n < G; n++) {
            float2 p0 = unpack2(acc0[n]);
            float2 p1 = unpack2(acc1[n]);
            float t0 = p0.x + p0.y;
            float t1 = p1.x + p1.y;
#pragma unroll
            for (int off = 16; off; off >>= 1) {
                t0 += __shfl_xor_sync(0xffffffffu, t0, off);
                t1 += __shfl_xor_sync(0xffffffffu, t1, off);
            }
            const float bias = __ldg(b + e0 + n);
            z0[n] = t0 + bias;
            z1[n] = t1 + bias;
        }

        // --- serial tail: in-group strictly-lower-tri terms (<=28 FMAs) ---
        float o0[G], o1[G];
#pragma unroll
        for (int k = 0; k < G; k++) {
            float t0 = z0[k], t1 = z1[k];
#pragma unroll
            for (int j = 0; j < k; j++) {
                const float wv = __ldg(W + (size_t)(e0 + k) * N_TOT + (i0 + j));
                t0 += wv * o0[j];
                t1 += wv * o1[j];
            }
            o0[k] = sigmoid5(t0);
            o1[k] = sigmoid5(t1);
        }

        // --- commit group activations to smem (lane 0, vec4) ---
        if (lane == 0) {
            ((float4*)(s0 + e0))[0] = make_float4(o0[0], o0[1], o0[2], o0[3]);
            ((float4*)(s0 + e0))[1] = make_float4(o0[4], o0[5], o0[6], o0[7]);
            ((float4*)(s1 + e0))[0] = make_float4(o1[0], o1[1], o1[2], o1[3]);
            ((float4*)(s1 + e0))[1] = make_float4(o1[4], o1[5], o1[6], o1[7]);
        }
        __syncwarp();
        __syncthreads();   // keep warps convergent -> L1 dedups W across block
    }

    // --- emit last N_OUT columns ---
    {
        float4*       d0 = (float4*)(out + (size_t)r0 * N_OUT);
        float4*       d1 = (float4*)(out + (size_t)(r0 + 1) * N_OUT);
        const float4* q0 = (const float4*)(s0 + (GROW - N_OUT));
        const float4* q1 = (const float4*)(s1 + (GROW - N_OUT));
#pragma unroll
        for (int k = 0; k < N_OUT / 128; k++) {
            d0[k * 32 + lane] = q0[k * 32 + lane];
            d1[k * 32 + lane] = q1[k * 32 + lane];
        }
    }
}

extern "C" void kernel_launch(void* const* d_in, const int* in_sizes, int n_in,
                              void* d_out, int out_size)
{
    const float* x = (const float*)d_in[0];
    const float* W = (const float*)d_in[1];
    const float* b = (const float*)d_in[2];
    float* out = (float*)d_out;

    cudaFuncSetAttribute(neat_group_kernel,
                         cudaFuncAttributeMaxDynamicSharedMemorySize, SMEM_BYTES);
    neat_group_kernel<<<GRID, THREADS, SMEM_BYTES>>>(x, W, b, out);
}